// round 3
// baseline (speedup 1.0000x reference)
#include <cuda_runtime.h>

#define Bc   2
#define HIDc 128
#define NVc  16
#define Hh   361
#define Ww   720
#define HW   (Hh*Ww)          // 259920
#define NPIX (Bc*HW)          // 519840
#define Hp   (Hh+4)           // 365
#define Wp   (Ww+4)           // 724

// scratch (static device globals -- no allocation)
__device__ float g_proj[Bc*NVc*HW];   // down-projected velocities [B*NV, H, W]
__device__ float g_y[Bc*NVc*HW];      // interpolated + depthwise-scaled [B*NV, H, W]

// ---------------- packed f32x2 helpers (FFMA2) ----------------
static __device__ __forceinline__ unsigned long long pk2(float x, float y) {
    unsigned long long r;
    asm("mov.b64 %0, {%1, %2};" : "=l"(r) : "f"(x), "f"(y));
    return r;
}
static __device__ __forceinline__ void upk2(unsigned long long r, float& x, float& y) {
    asm("mov.b64 {%0, %1}, %2;" : "=f"(x), "=f"(y) : "l"(r));
}
static __device__ __forceinline__ unsigned long long ffma2(unsigned long long a,
                                                           unsigned long long b,
                                                           unsigned long long c) {
    unsigned long long d;
    asm("fma.rn.f32x2 %0, %1, %2, %3;" : "=l"(d) : "l"(a), "l"(b), "l"(c));
    return d;
}

// ---------------- K1: down projection (hidden[B,128,H,W] -> g_proj[B,16,H,W]) ----------------
// proj = down_w @ hidden + down_b. Pole fix commutes with the linear projection,
// so it is applied afterwards on proj (K2). 4 pixels per thread, FFMA2.
__global__ void __launch_bounds__(256) k_down(const float* __restrict__ x,
                                              const float* __restrict__ dw,
                                              const float* __restrict__ db) {
    __shared__ __align__(16) unsigned long long wsh[HIDc*NVc];  // [c][v], (w,w) pairs
    int tid = threadIdx.x;
    for (int i = tid; i < HIDc*NVc; i += 256) {
        int c = i >> 4, v = i & 15;
        float w = dw[v*HIDc + c];
        wsh[i] = pk2(w, w);
    }
    __syncthreads();

    int t = blockIdx.x*256 + tid;         // pixel-quad id
    int q0 = t * 4;
    if (q0 >= NPIX) return;
    int b = q0 / HW;
    int p = q0 - b*HW;                    // HW % 4 == 0 -> quad never crosses b

    const float* xb = x + (size_t)b*HIDc*HW + p;

    unsigned long long acc[NVc*2];        // acc[2v] = (px0,px1), acc[2v+1] = (px2,px3)
    #pragma unroll
    for (int v = 0; v < NVc; v++) {
        float bb = db[v];
        acc[2*v]   = pk2(bb, bb);
        acc[2*v+1] = acc[2*v];
    }

    #pragma unroll 4
    for (int c = 0; c < HIDc; c++) {
        float4 xv = *(const float4*)(xb + (size_t)c*HW);
        unsigned long long x0 = pk2(xv.x, xv.y);
        unsigned long long x1 = pk2(xv.z, xv.w);
        const ulonglong2* wr = (const ulonglong2*)&wsh[c*NVc];
        #pragma unroll
        for (int j = 0; j < 8; j++) {
            ulonglong2 ww = wr[j];
            acc[4*j+0] = ffma2(x0, ww.x, acc[4*j+0]);
            acc[4*j+1] = ffma2(x1, ww.x, acc[4*j+1]);
            acc[4*j+2] = ffma2(x0, ww.y, acc[4*j+2]);
            acc[4*j+3] = ffma2(x1, ww.y, acc[4*j+3]);
        }
    }

    float* pb = g_proj + (size_t)b*NVc*HW + p;
    #pragma unroll
    for (int v = 0; v < NVc; v++) {
        float4 r;
        upk2(acc[2*v],   r.x, r.y);
        upk2(acc[2*v+1], r.z, r.w);
        *(float4*)(pb + (size_t)v*HW) = r;
    }
}

// ---------------- K2/K5: pole fix (rows 0 and H-1 -> longitude mean) ----------------
// Operates on a [C, H, W] tensor. blockIdx.x = chan*2 + which_pole.
__global__ void __launch_bounds__(256) k_pole(float* pext, int use_proj) {
    float* base = use_proj ? g_proj : pext;
    int c   = blockIdx.x >> 1;
    int row = (blockIdx.x & 1) ? (Hh - 1) : 0;
    float* rp = base + ((size_t)c*Hh + row)*Ww;

    __shared__ float sh[256];
    float s = 0.0f;
    for (int i = threadIdx.x; i < Ww; i += 256) s += rp[i];
    sh[threadIdx.x] = s;
    __syncthreads();
    for (int o = 128; o > 0; o >>= 1) {
        if (threadIdx.x < o) sh[threadIdx.x] += sh[threadIdx.x + o];
        __syncthreads();
    }
    float m = sh[0] / (float)Ww;
    for (int i = threadIdx.x; i < Ww; i += 256) rp[i] = m;
}

// ---------------- K3: departure point + geo-padded bicubic + depthwise ----------------
// One thread per (b, v, h, w). Geo-cyclic padding handled by index mapping:
//   padded row yp:   yp in [2, H+2) -> row yp-2, no shift
//                    yp in [0, 2)   -> row 1-yp,    +W/2 lon shift (pole reflect)
//                    yp >= H+2      -> row 2H+1-yp, +W/2 lon shift
//   padded col xp -> (xp-2) mod W (cyclic), +360 mod W when shifted.
// All 4x4 taps are provably inside the padded domain, so the 'zeros' padding
// branch of grid_sample never contributes.
__global__ void __launch_bounds__(256) k_advect(const float* __restrict__ uin,
                                                const float* __restrict__ vin,
                                                const float* __restrict__ dtp,
                                                const float* __restrict__ latg,
                                                const float* __restrict__ lonG,
                                                const float* __restrict__ dww,
                                                const float* __restrict__ dwb) {
    int idx = blockIdx.x*256 + threadIdx.x;
    if (idx >= Bc*NVc*HW) return;
    int bv = idx / HW;
    int p  = idx - bv*HW;

    float uu = uin[idx];
    float vv = vin[idx];
    float dt = __ldg(dtp);
    float lat_g = latg[p];
    float lon_g = lonG[p];
    float min_lat = __ldg(&latg[0]);
    float max_lat = __ldg(&latg[(Hh-1)*Ww]);
    float min_lon = __ldg(&lonG[0]);
    float max_lon = __ldg(&lonG[Ww-1]);
    float d_lat = max_lat - min_lat;
    float d_lon = max_lon - min_lon;

    float lon_pr = -uu * dt;
    float lat_pr = -vv * dt;
    float slp, clp, slo, clo, slg, clg;
    __sincosf(lat_pr, &slp, &clp);
    __sincosf(lon_pr, &slo, &clo);
    __sincosf(lat_g,  &slg, &clg);

    float sin_lat = slp*clg + clp*clo*slg;
    const float CL = 1.0f - 1e-7f;
    sin_lat = fminf(fmaxf(sin_lat, -CL), CL);
    float lat_dep = asinf(sin_lat);

    float num = clp * slo;
    float den = clp*clo*clg - slp*slg;
    const float TWO_PI = 6.28318530717958647692f;
    float lon_dep = lon_g + atan2f(num, den);
    lon_dep = fmodf(lon_dep + TWO_PI, TWO_PI);   // numerator >= 0 -> matches jnp.remainder

    float pix_x = (lon_dep - min_lon) / d_lon * (float)(Ww - 1);
    float pix_y = (lat_dep - min_lat) / d_lat * (float)(Hh - 1);
    // normalize/unnormalize round trip (align_corners=True), replicated in fp32
    float gx = 2.0f * ((pix_x + 2.0f) / (float)(Wp - 1)) - 1.0f;
    float gy = 2.0f * ((pix_y + 2.0f) / (float)(Hp - 1)) - 1.0f;
    float ix = (gx + 1.0f) * 0.5f * (float)(Wp - 1);
    float iy = (gy + 1.0f) * 0.5f * (float)(Hp - 1);

    float xf = floorf(ix), yf = floorf(iy);
    float tx = ix - xf,    ty = iy - yf;
    int x0 = (int)xf, y0 = (int)yf;
    x0 = min(max(x0, 1), Ww + 1);   // safety clamp (no-op in normal operation)
    y0 = min(max(y0, 1), Hh + 1);

    const float Aa = -0.75f;
    float t1 = tx + 1.0f, t2 = 1.0f - tx, t3 = 2.0f - tx;
    float wx0 = ((Aa*t1 - 5.0f*Aa)*t1 + 8.0f*Aa)*t1 - 4.0f*Aa;
    float wx1 = ((Aa + 2.0f)*tx - (Aa + 3.0f))*tx*tx + 1.0f;
    float wx2 = ((Aa + 2.0f)*t2 - (Aa + 3.0f))*t2*t2 + 1.0f;
    float wx3 = ((Aa*t3 - 5.0f*Aa)*t3 + 8.0f*Aa)*t3 - 4.0f*Aa;
    float s1 = ty + 1.0f, s2 = 1.0f - ty, s3 = 2.0f - ty;
    float wy0 = ((Aa*s1 - 5.0f*Aa)*s1 + 8.0f*Aa)*s1 - 4.0f*Aa;
    float wy1 = ((Aa + 2.0f)*ty - (Aa + 3.0f))*ty*ty + 1.0f;
    float wy2 = ((Aa + 2.0f)*s2 - (Aa + 3.0f))*s2*s2 + 1.0f;
    float wy3 = ((Aa*s3 - 5.0f*Aa)*s3 + 8.0f*Aa)*s3 - 4.0f*Aa;

    // column indices: unshifted (cyclic) and pole-shifted (+W/2)
    int cbase = x0 - 3;                      // (x0-1+dx) - 2, dx=0
    int cb0 = cbase;     if (cb0 <  0)  cb0 += Ww; if (cb0 >= Ww) cb0 -= Ww;
    int cb1 = cbase + 1; if (cb1 <  0)  cb1 += Ww; if (cb1 >= Ww) cb1 -= Ww;
    int cb2 = cbase + 2; if (cb2 <  0)  cb2 += Ww; if (cb2 >= Ww) cb2 -= Ww;
    int cb3 = cbase + 3; if (cb3 <  0)  cb3 += Ww; if (cb3 >= Ww) cb3 -= Ww;
    int cs0 = cb0 + Ww/2; if (cs0 >= Ww) cs0 -= Ww;
    int cs1 = cb1 + Ww/2; if (cs1 >= Ww) cs1 -= Ww;
    int cs2 = cb2 + Ww/2; if (cs2 >= Ww) cs2 -= Ww;
    int cs3 = cb3 + Ww/2; if (cs3 >= Ww) cs3 -= Ww;

    const float* pr = g_proj + (size_t)bv*HW;
    float acc = 0.0f;

#define ROWSUM(WYV, DY) do {                                                   \
        int yy = y0 - 1 + (DY);                                                \
        int yi = yy - 2;                                                       \
        int r, shf;                                                            \
        if (yi < 0)        { r = 1 - yy;        shf = 1; }                     \
        else if (yi >= Hh) { r = 2*Hh + 1 - yy; shf = 1; }                     \
        else               { r = yi;            shf = 0; }                     \
        const float* row = pr + (size_t)r*Ww;                                  \
        int c0 = shf ? cs0 : cb0;                                              \
        int c1 = shf ? cs1 : cb1;                                              \
        int c2 = shf ? cs2 : cb2;                                              \
        int c3 = shf ? cs3 : cb3;                                              \
        float s = fmaf(wx3, row[c3],                                           \
                  fmaf(wx2, row[c2],                                           \
                  fmaf(wx1, row[c1], wx0*row[c0])));                           \
        acc = fmaf((WYV), s, acc);                                             \
    } while (0)

    ROWSUM(wy0, 0);
    ROWSUM(wy1, 1);
    ROWSUM(wy2, 2);
    ROWSUM(wy3, 3);
#undef ROWSUM

    int v = bv & (NVc - 1);
    g_y[idx] = acc * __ldg(&dww[v]) + __ldg(&dwb[v]);
}

// ---------------- K4: up projection (g_y[B,16,H,W] -> out[B,128,H,W]) ----------------
// 4 pixels per thread, FFMA2 over v-pairs, float4 loads/stores.
__global__ void __launch_bounds__(256) k_up(const float* __restrict__ uw,
                                            const float* __restrict__ ub,
                                            float* __restrict__ out) {
    __shared__ __align__(16) unsigned long long wsh[HIDc*NVc];  // [o][v], (w,w) pairs
    __shared__ float bsh[HIDc];
    int tid = threadIdx.x;
    for (int i = tid; i < HIDc*NVc; i += 256) {
        float w = uw[i];                 // up_w row-major [o][v]
        wsh[i] = pk2(w, w);
    }
    if (tid < HIDc) bsh[tid] = ub[tid];
    __syncthreads();

    int t = blockIdx.x*256 + tid;
    int q0 = t * 4;
    if (q0 >= NPIX) return;
    int b = q0 / HW;
    int p = q0 - b*HW;

    const float* yb = g_y + (size_t)b*NVc*HW + p;
    unsigned long long y0p[NVc], y1p[NVc];
    #pragma unroll
    for (int v = 0; v < NVc; v++) {
        float4 yv = *(const float4*)(yb + (size_t)v*HW);
        y0p[v] = pk2(yv.x, yv.y);
        y1p[v] = pk2(yv.z, yv.w);
    }

    float* ob = out + (size_t)b*HIDc*HW + p;
    #pragma unroll 2
    for (int o = 0; o < HIDc; o++) {
        float bias = bsh[o];
        unsigned long long a0 = pk2(bias, bias);
        unsigned long long a1 = a0;
        const ulonglong2* wr = (const ulonglong2*)&wsh[o*NVc];
        #pragma unroll
        for (int j = 0; j < 8; j++) {
            ulonglong2 ww = wr[j];
            a0 = ffma2(y0p[2*j],   ww.x, a0);
            a1 = ffma2(y1p[2*j],   ww.x, a1);
            a0 = ffma2(y0p[2*j+1], ww.y, a0);
            a1 = ffma2(y1p[2*j+1], ww.y, a1);
        }
        float4 r;
        upk2(a0, r.x, r.y);
        upk2(a1, r.z, r.w);
        *(float4*)(ob + (size_t)o*HW) = r;
    }
}

// ---------------- launcher ----------------
extern "C" void kernel_launch(void* const* d_in, const int* in_sizes, int n_in,
                              void* d_out, int out_size) {
    const float* hidden = (const float*)d_in[0];
    const float* u      = (const float*)d_in[1];
    const float* v      = (const float*)d_in[2];
    const float* dt     = (const float*)d_in[3];
    const float* latg   = (const float*)d_in[4];
    const float* lonG   = (const float*)d_in[5];
    const float* down_w = (const float*)d_in[6];
    const float* down_b = (const float*)d_in[7];
    const float* dw_w   = (const float*)d_in[8];
    const float* dw_b   = (const float*)d_in[9];
    const float* up_w   = (const float*)d_in[10];
    const float* up_b   = (const float*)d_in[11];
    float* out = (float*)d_out;

    int quad_blocks = (NPIX/4 + 255) / 256;                   // 508
    k_down<<<quad_blocks, 256>>>(hidden, down_w, down_b);
    k_pole<<<Bc*NVc*2, 256>>>(nullptr, 1);                    // fix g_proj poles
    k_advect<<<(Bc*NVc*HW + 255)/256, 256>>>(u, v, dt, latg, lonG, dw_w, dw_b);
    k_up<<<quad_blocks, 256>>>(up_w, up_b, out);
    k_pole<<<Bc*HIDc*2, 256>>>(out, 0);                       // fix output poles
}